// round 10
// baseline (speedup 1.0000x reference)
#include <cuda_runtime.h>
#include <cuda_fp16.h>
#include <math.h>
#include <stdint.h>

// ContinuousRelativePositionalBias — Round 10: R9 (A fragments computed
// in-register, B-only crossbar) + 2x warps per SM for latency hiding:
// 2 CTAs x 256 threads, warp grid 4(wm) x 2(wn), warp tile 32M x 64N.
// B traffic per point unchanged from R9; A-gen duplicated across wn (cheap).

#define ID 512
#define JD 512
#define DD 128
#define MROWS 128
#define NTHREADS 256
#define GRIDSZ 296
#define NITER 8192

#define SWZ(row, chunk) ((unsigned)(row) * 256u + ((((unsigned)(chunk)) ^ ((unsigned)(row) & 7u)) << 4))

// smem byte offsets
#define OFF_W2    0          // 32KB fp16 W2^T [n][k] swizzled
#define OFF_RED   32768      // 2 x 256 float4 = 8KB (dbl-buffered, 2 wn partials)
#define OFF_BIAS  40960      // 2 x 128 float4 = 4KB (dbl-buffered)
#define OFF_W1P   45056      // 128 float4 {w0,w1,w2,b1}
#define OFF_B2    47104      // 128 floats
#define OFF_W3    47616      // 512 floats [e][o]
#define OFF_B3    49664      // 4 floats
#define SMEM_BYTES 49680

__device__ __align__(16) uint8_t g_w2h[32768];

__global__ void prep_w2(const float* __restrict__ W2) {
    int idx = blockIdx.x * blockDim.x + threadIdx.x;
    if (idx >= DD * DD) return;
    int n = idx >> 7, k = idx & 127;
    unsigned byte = SWZ(n, k >> 3) + (unsigned)(k & 7) * 2u;
    *(uint16_t*)(g_w2h + byte) = __half_as_ushort(__float2half_rn(W2[k * DD + n]));
}

__device__ __forceinline__ uint32_t smem_u32(const void* p) {
    uint32_t a;
    asm("{ .reg .u64 t; cvta.to.shared.u64 t, %1; cvt.u32.u64 %0, t; }" : "=r"(a) : "l"(p));
    return a;
}
__device__ __forceinline__ void ldsm_x4(uint32_t* r, uint32_t addr) {
    asm volatile("ldmatrix.sync.aligned.m8n8.x4.shared.b16 {%0,%1,%2,%3}, [%4];"
                 : "=r"(r[0]), "=r"(r[1]), "=r"(r[2]), "=r"(r[3]) : "r"(addr));
}
__device__ __forceinline__ void mma_fp16(float* c, const uint32_t* a, uint32_t b0, uint32_t b1) {
    asm volatile("mma.sync.aligned.m16n8k16.row.col.f32.f16.f16.f32 "
                 "{%0,%1,%2,%3}, {%4,%5,%6,%7}, {%8,%9}, {%0,%1,%2,%3};"
                 : "+f"(c[0]), "+f"(c[1]), "+f"(c[2]), "+f"(c[3])
                 : "r"(a[0]), "r"(a[1]), "r"(a[2]), "r"(a[3]), "r"(b0), "r"(b1));
}
#define CP_ASYNC16(dst, src) \
    asm volatile("cp.async.cg.shared.global [%0], [%1], 16;" :: "r"(dst), "l"(src) : "memory")
#define CP_ASYNC_COMMIT() asm volatile("cp.async.commit_group;" ::: "memory")
#define CP_ASYNC_WAIT0()  asm volatile("cp.async.wait_group 0;" ::: "memory")

__device__ __forceinline__ float relu3(const float4 bs, const float4 w) {
    return fmaxf(fmaf(bs.x, w.x, fmaf(bs.y, w.y, fmaf(bs.z, w.z, w.w))), 0.0f);
}
__device__ __forceinline__ uint32_t h2pack(float a, float b) {
    __half2 h = __floats2half2_rn(a, b);
    return *(uint32_t*)&h;
}

__device__ __forceinline__ void compute_bias(int it, float4* sB4,
                                             const float* __restrict__ grid_q,
                                             const float* __restrict__ grid_kv, int tid) {
    if (tid < MROWS) {
        const int jt = it & 3;
        const int i  = (it >> 2) & (ID - 1);
        const int b  = it >> 11;
        const int j  = jt * MROWS + tid;
        const float q0 = __ldg(grid_q + i * 3 + 0);
        const float q1 = __ldg(grid_q + i * 3 + 1);
        const float q2 = __ldg(grid_q + i * 3 + 2);
        const float p0 = q0 - grid_kv[(b * JD + j) * 3 + 0];
        const float p1 = q1 - grid_kv[(b * JD + j) * 3 + 1];
        const float p2 = q2 - grid_kv[(b * JD + j) * 3 + 2];
        sB4[tid] = make_float4(copysignf(__logf(1.0f + fabsf(p0)), p0),
                               copysignf(__logf(1.0f + fabsf(p1)), p1),
                               copysignf(__logf(1.0f + fabsf(p2)), p2), 0.0f);
    }
}

// ---------------- main persistent kernel ----------------
__global__ __launch_bounds__(NTHREADS, 2)
void crpb_kernel(const float* __restrict__ grid_q,
                 const float* __restrict__ grid_kv,
                 const float* __restrict__ W1, const float* __restrict__ b1,
                 const float* __restrict__ b2,
                 const float* __restrict__ W3, const float* __restrict__ b3,
                 float* __restrict__ out)
{
    extern __shared__ __align__(1024) char smem[];
    float4* sW1p  = (float4*)(smem + OFF_W1P);
    float*  sb2   = (float*)(smem + OFF_B2);
    float*  sW3   = (float*)(smem + OFF_W3);
    float*  sb3   = (float*)(smem + OFF_B3);
    float4* sBias = (float4*)(smem + OFF_BIAS);   // 2 x 128
    float4* sRed  = (float4*)(smem + OFF_RED);    // 2 x 256

    const int tid  = threadIdx.x;
    const int lane = tid & 31;
    const int wid  = tid >> 5;
    const int wm   = wid & 3;          // M: rows wm*32..+31
    const int wn   = wid >> 2;         // N: cols wn*64..+63

    // ---- one-time prologue ----
    if (tid < DD) {
        sW1p[tid] = make_float4(W1[tid], W1[DD + tid], W1[2 * DD + tid], b1[tid]);
        sb2[tid]  = b2[tid];
        reinterpret_cast<float4*>(sW3)[tid] = reinterpret_cast<const float4*>(W3)[tid];
    }
    if (tid < 4) sb3[tid] = b3[tid];
    {
        uint32_t dst = smem_u32(smem + OFF_W2) + tid * 16;
        const char* src = (const char*)g_w2h + tid * 16;
        #pragma unroll
        for (int it = 0; it < 8; ++it) CP_ASYNC16(dst + it * 4096, src + it * 4096);
        CP_ASYNC_COMMIT();
    }

    const int nt = (NITER - blockIdx.x + GRIDSZ - 1) / GRIDSZ;
    #define TILE_AT(k) (blockIdx.x + (k) * GRIDSZ)

    compute_bias(TILE_AT(0), sBias, grid_q, grid_kv, tid);
    CP_ASYNC_WAIT0();
    __syncthreads();

    const int g  = lane >> 2;
    const int t4 = lane & 3;
    const int brow_base = wn * 64 + (lane & 7) + ((lane >> 4) << 3);
    const unsigned bsel = (lane >> 3) & 1;
    const uint32_t w2b = smem_u32(smem + OFF_W2);

    for (int k = 0; k < nt; ++k) {
        const float4* bcur = sBias + (k & 1) * 128;
        if (k + 1 < nt)
            compute_bias(TILE_AT(k + 1), sBias + ((k + 1) & 1) * 128, grid_q, grid_kv, tid);

        // bias rows for this warp's 32 rows (broadcast LDS)
        const float4 bsr0 = bcur[wm * 32 + g];
        const float4 bsr1 = bcur[wm * 32 + 8 + g];
        const float4 bsr2 = bcur[wm * 32 + 16 + g];
        const float4 bsr3 = bcur[wm * 32 + 24 + g];

        float acc[2][8][4];
        #pragma unroll
        for (int mt = 0; mt < 2; ++mt)
            #pragma unroll
            for (int n8 = 0; n8 < 8; ++n8)
                #pragma unroll
                for (int c = 0; c < 4; ++c) acc[mt][n8][c] = 0.0f;

        #pragma unroll
        for (int kc = 0; kc < 8; ++kc) {
            const int c0 = kc * 16 + 2 * t4;
            const float4 w0 = sW1p[c0];
            const float4 w1 = sW1p[c0 + 1];
            const float4 w8 = sW1p[c0 + 8];
            const float4 w9 = sW1p[c0 + 9];

            uint32_t A[2][4];
            A[0][0] = h2pack(relu3(bsr0, w0), relu3(bsr0, w1));
            A[0][1] = h2pack(relu3(bsr1, w0), relu3(bsr1, w1));
            A[0][2] = h2pack(relu3(bsr0, w8), relu3(bsr0, w9));
            A[0][3] = h2pack(relu3(bsr1, w8), relu3(bsr1, w9));
            A[1][0] = h2pack(relu3(bsr2, w0), relu3(bsr2, w1));
            A[1][1] = h2pack(relu3(bsr3, w0), relu3(bsr3, w1));
            A[1][2] = h2pack(relu3(bsr2, w8), relu3(bsr2, w9));
            A[1][3] = h2pack(relu3(bsr3, w8), relu3(bsr3, w9));

            #pragma unroll
            for (int ng = 0; ng < 4; ++ng) {
                uint32_t B[4];
                ldsm_x4(B, w2b + SWZ(ng * 16 + brow_base, kc * 2 + bsel));
                mma_fp16(acc[0][2 * ng],     A[0], B[0], B[1]);
                mma_fp16(acc[0][2 * ng + 1], A[0], B[2], B[3]);
                mma_fp16(acc[1][2 * ng],     A[1], B[0], B[1]);
                mma_fp16(acc[1][2 * ng + 1], A[1], B[2], B[3]);
            }
        }

        // ---- epilogue: relu(H2+b2) @ W3 over this warp's 64 cols ----
        float4* redc = sRed + (k & 1) * 256;
        #pragma unroll
        for (int mt = 0; mt < 2; ++mt) {
            float ov[2][4] = {{0,0,0,0},{0,0,0,0}};
            #pragma unroll
            for (int n8 = 0; n8 < 8; ++n8) {
                const int e0 = wn * 64 + n8 * 8 + 2 * t4;
                const float2 b2v = *(const float2*)(sb2 + e0);
                const float4 w30 = *(const float4*)(sW3 + e0 * 4);
                const float4 w31 = *(const float4*)(sW3 + (e0 + 1) * 4);
                float h00 = fmaxf(acc[mt][n8][0] + b2v.x, 0.0f);
                float h01 = fmaxf(acc[mt][n8][1] + b2v.y, 0.0f);
                float h10 = fmaxf(acc[mt][n8][2] + b2v.x, 0.0f);
                float h11 = fmaxf(acc[mt][n8][3] + b2v.y, 0.0f);
                ov[0][0] = fmaf(h00, w30.x, fmaf(h01, w31.x, ov[0][0]));
                ov[0][1] = fmaf(h00, w30.y, fmaf(h01, w31.y, ov[0][1]));
                ov[0][2] = fmaf(h00, w30.z, fmaf(h01, w31.z, ov[0][2]));
                ov[0][3] = fmaf(h00, w30.w, fmaf(h01, w31.w, ov[0][3]));
                ov[1][0] = fmaf(h10, w30.x, fmaf(h11, w31.x, ov[1][0]));
                ov[1][1] = fmaf(h10, w30.y, fmaf(h11, w31.y, ov[1][1]));
                ov[1][2] = fmaf(h10, w30.z, fmaf(h11, w31.z, ov[1][2]));
                ov[1][3] = fmaf(h10, w30.w, fmaf(h11, w31.w, ov[1][3]));
            }
            #pragma unroll
            for (int h = 0; h < 2; ++h)
                #pragma unroll
                for (int o = 0; o < 4; ++o) {
                    float v = ov[h][o];
                    v += __shfl_xor_sync(0xFFFFFFFF, v, 1);
                    v += __shfl_xor_sync(0xFFFFFFFF, v, 2);
                    ov[h][o] = v;
                }
            if (t4 == 0) {
                redc[wn * 128 + wm * 32 + mt * 16 + g]     = make_float4(ov[0][0], ov[0][1], ov[0][2], ov[0][3]);
                redc[wn * 128 + wm * 32 + mt * 16 + 8 + g] = make_float4(ov[1][0], ov[1][1], ov[1][2], ov[1][3]);
            }
        }
        __syncthreads();   // single barrier per iteration

        if (tid < MROWS) {
            const float4 r0 = redc[tid];
            const float4 r1 = redc[128 + tid];
            const int it = TILE_AT(k);
            const int jt = it & 3;
            const int i  = (it >> 2) & (ID - 1);
            const int b  = it >> 11;
            const long base = ((long)(b * 4) * ID + i) * JD + jt * MROWS + tid;
            const long os   = (long)ID * JD;
            out[base]          = r0.x + r1.x + sb3[0];
            out[base + os]     = r0.y + r1.y + sb3[1];
            out[base + 2 * os] = r0.z + r1.z + sb3[2];
            out[base + 3 * os] = r0.w + r1.w + sb3[3];
        }
    }
}

extern "C" void kernel_launch(void* const* d_in, const int* in_sizes, int n_in,
                              void* d_out, int out_size)
{
    const float* grid_q  = (const float*)d_in[0];
    const float* grid_kv = (const float*)d_in[1];
    const float* W1      = (const float*)d_in[2];
    const float* b1      = (const float*)d_in[3];
    const float* W2      = (const float*)d_in[4];
    const float* b2      = (const float*)d_in[5];
    const float* W3      = (const float*)d_in[6];
    const float* b3      = (const float*)d_in[7];
    float* out = (float*)d_out;

    prep_w2<<<DD * DD / 256, 256>>>(W2);

    cudaFuncSetAttribute(crpb_kernel,
                         cudaFuncAttributeMaxDynamicSharedMemorySize, SMEM_BYTES);
    crpb_kernel<<<GRIDSZ, NTHREADS, SMEM_BYTES>>>(
        grid_q, grid_kv, W1, b1, b2, W3, b3, out);
}

// round 11
// speedup vs baseline: 1.2445x; 1.2445x over previous
#include <cuda_runtime.h>
#include <cuda_fp16.h>
#include <math.h>
#include <stdint.h>

// ContinuousRelativePositionalBias — Round 11: layer 1 moved onto tensor cores.
// H1 = relu(bias_pad @ W1_aug) computed per-kc as tiny K=16 MMAs whose C
// fragments ARE the next GEMM's A fragments (relu+pack only, no smem).
// b1 folded via homogeneous column (bias.w = 1, W1_aug row3 = b1).
// Keeps R9 structure: 2 x 128-thread CTAs/SM, warp tile 32Mx128N, B-only
// crossbar, 1 barrier/iter.

#define ID 512
#define JD 512
#define DD 128
#define MROWS 128
#define NTHREADS 128
#define GRIDSZ 296
#define NITER 8192

#define SWZ(row, chunk) ((unsigned)(row) * 256u + ((((unsigned)(chunk)) ^ ((unsigned)(row) & 7u)) << 4))

// smem byte offsets
#define OFF_W2    0          // 32KB fp16 W2^T [n][k] swizzled
#define OFF_RED   32768      // 2 x 128 float4 (dbl-buffered)
#define OFF_BIAS  36864      // 2 x 128 float4 (dbl-buffered)
#define OFF_W1AUG 40960      // 128 x 16 fp16 = 4KB  (W1_aug^T: [n][k], k=16 padded)
#define OFF_B2    45056      // 128 floats
#define OFF_W3    45568      // 512 floats [e][o]
#define OFF_B3    47616      // 4 floats
#define SMEM_BYTES 47632

__device__ __align__(16) uint8_t g_w2h[32768];

__global__ void prep_w2(const float* __restrict__ W2) {
    int idx = blockIdx.x * blockDim.x + threadIdx.x;
    if (idx >= DD * DD) return;
    int n = idx >> 7, k = idx & 127;
    unsigned byte = SWZ(n, k >> 3) + (unsigned)(k & 7) * 2u;
    *(uint16_t*)(g_w2h + byte) = __half_as_ushort(__float2half_rn(W2[k * DD + n]));
}

__device__ __forceinline__ uint32_t smem_u32(const void* p) {
    uint32_t a;
    asm("{ .reg .u64 t; cvta.to.shared.u64 t, %1; cvt.u32.u64 %0, t; }" : "=r"(a) : "l"(p));
    return a;
}
__device__ __forceinline__ void ldsm_x4(uint32_t* r, uint32_t addr) {
    asm volatile("ldmatrix.sync.aligned.m8n8.x4.shared.b16 {%0,%1,%2,%3}, [%4];"
                 : "=r"(r[0]), "=r"(r[1]), "=r"(r[2]), "=r"(r[3]) : "r"(addr));
}
__device__ __forceinline__ void mma_fp16(float* c, const uint32_t* a, uint32_t b0, uint32_t b1) {
    asm volatile("mma.sync.aligned.m16n8k16.row.col.f32.f16.f16.f32 "
                 "{%0,%1,%2,%3}, {%4,%5,%6,%7}, {%8,%9}, {%0,%1,%2,%3};"
                 : "+f"(c[0]), "+f"(c[1]), "+f"(c[2]), "+f"(c[3])
                 : "r"(a[0]), "r"(a[1]), "r"(a[2]), "r"(a[3]), "r"(b0), "r"(b1));
}
#define CP_ASYNC16(dst, src) \
    asm volatile("cp.async.cg.shared.global [%0], [%1], 16;" :: "r"(dst), "l"(src) : "memory")
#define CP_ASYNC_COMMIT() asm volatile("cp.async.commit_group;" ::: "memory")
#define CP_ASYNC_WAIT0()  asm volatile("cp.async.wait_group 0;" ::: "memory")

__device__ __forceinline__ uint32_t h2pack(float a, float b) {
    __half2 h = __floats2half2_rn(a, b);
    return *(uint32_t*)&h;
}

__device__ __forceinline__ void compute_bias(int it, float4* sB4,
                                             const float* __restrict__ grid_q,
                                             const float* __restrict__ grid_kv, int tid) {
    const int jt = it & 3;
    const int i  = (it >> 2) & (ID - 1);
    const int b  = it >> 11;
    const int j  = jt * MROWS + tid;
    const float q0 = __ldg(grid_q + i * 3 + 0);
    const float q1 = __ldg(grid_q + i * 3 + 1);
    const float q2 = __ldg(grid_q + i * 3 + 2);
    const float p0 = q0 - grid_kv[(b * JD + j) * 3 + 0];
    const float p1 = q1 - grid_kv[(b * JD + j) * 3 + 1];
    const float p2 = q2 - grid_kv[(b * JD + j) * 3 + 2];
    sB4[tid] = make_float4(copysignf(__logf(1.0f + fabsf(p0)), p0),
                           copysignf(__logf(1.0f + fabsf(p1)), p1),
                           copysignf(__logf(1.0f + fabsf(p2)), p2), 1.0f);  // w=1: b1 column
}

// ---------------- main persistent kernel ----------------
__global__ __launch_bounds__(NTHREADS, 2)
void crpb_kernel(const float* __restrict__ grid_q,
                 const float* __restrict__ grid_kv,
                 const float* __restrict__ W1, const float* __restrict__ b1,
                 const float* __restrict__ b2,
                 const float* __restrict__ W3, const float* __restrict__ b3,
                 float* __restrict__ out)
{
    extern __shared__ __align__(1024) char smem[];
    float*  sb2   = (float*)(smem + OFF_B2);
    float*  sW3   = (float*)(smem + OFF_W3);
    float*  sb3   = (float*)(smem + OFF_B3);
    float4* sBias = (float4*)(smem + OFF_BIAS);   // 2 x 128
    float4* sRed  = (float4*)(smem + OFF_RED);    // 2 x 128

    const int tid  = threadIdx.x;
    const int lane = tid & 31;
    const int wid  = tid >> 5;         // 4 warps stacked in M

    // ---- one-time prologue ----
    if (tid < DD) {
        sb2[tid] = b2[tid];
        reinterpret_cast<float4*>(sW3)[tid] = reinterpret_cast<const float4*>(W3)[tid];
        // W1_aug^T: [n=tid][k], k: 0..2 = W1 rows, 3 = b1, 4..15 = 0
        __half* row = (__half*)(smem + OFF_W1AUG) + tid * 16;
        row[0] = __float2half_rn(W1[tid]);
        row[1] = __float2half_rn(W1[DD + tid]);
        row[2] = __float2half_rn(W1[2 * DD + tid]);
        row[3] = __float2half_rn(b1[tid]);
        #pragma unroll
        for (int q = 4; q < 16; ++q) row[q] = __float2half_rn(0.0f);
    }
    if (tid < 4) sb3[tid] = b3[tid];
    {
        uint32_t dst = smem_u32(smem + OFF_W2) + tid * 16;
        const char* src = (const char*)g_w2h + tid * 16;
        #pragma unroll
        for (int it = 0; it < 16; ++it) CP_ASYNC16(dst + it * 2048, src + it * 2048);
        CP_ASYNC_COMMIT();
    }

    const int nt = (NITER - blockIdx.x + GRIDSZ - 1) / GRIDSZ;
    #define TILE_AT(k) (blockIdx.x + (k) * GRIDSZ)

    compute_bias(TILE_AT(0), sBias, grid_q, grid_kv, tid);
    CP_ASYNC_WAIT0();
    __syncthreads();

    const int g  = lane >> 2;
    const int t4 = lane & 3;
    const int brow_base = (lane & 7) + ((lane >> 4) << 3);
    const unsigned bsel = (lane >> 3) & 1;
    const uint32_t w2b = smem_u32(smem + OFF_W2);

    // W1_aug B fragments: persistent in registers for the whole kernel.
    // Same [n][k] non-trans ldsm pattern as W2 (rows 32B wide, no swizzle).
    uint32_t W1B[8][4];
    {
        const uint32_t wb = smem_u32(smem + OFF_W1AUG);
        #pragma unroll
        for (int ng = 0; ng < 8; ++ng)
            ldsm_x4(W1B[ng], wb + (unsigned)(ng * 16 + brow_base) * 32u + bsel * 16u);
    }

    for (int k = 0; k < nt; ++k) {
        const float4* bcur = sBias + (k & 1) * 128;
        if (k + 1 < nt)
            compute_bias(TILE_AT(k + 1), sBias + ((k + 1) & 1) * 128, grid_q, grid_kv, tid);

        // bias A-fragments for this warp's 32 rows (built once per iter).
        // a-layout for K=16 mma: a0 = row g cols{2t4,2t4+1}; a1 = row g+8; a2=a3=0.
        // cols 0..3 of bias_pad = {bs0,bs1,bs2,1}; cols >=4 are zero.
        uint32_t ab[2][2];
        {
            const float4 r0 = bcur[wid * 32 + g];
            const float4 r1 = bcur[wid * 32 + 8 + g];
            const float4 r2 = bcur[wid * 32 + 16 + g];
            const float4 r3 = bcur[wid * 32 + 24 + g];
            ab[0][0] = (t4 == 0) ? h2pack(r0.x, r0.y) : (t4 == 1) ? h2pack(r0.z, r0.w) : 0u;
            ab[0][1] = (t4 == 0) ? h2pack(r1.x, r1.y) : (t4 == 1) ? h2pack(r1.z, r1.w) : 0u;
            ab[1][0] = (t4 == 0) ? h2pack(r2.x, r2.y) : (t4 == 1) ? h2pack(r2.z, r2.w) : 0u;
            ab[1][1] = (t4 == 0) ? h2pack(r3.x, r3.y) : (t4 == 1) ? h2pack(r3.z, r3.w) : 0u;
        }

        float acc[2][16][4];
        #pragma unroll
        for (int mt = 0; mt < 2; ++mt)
            #pragma unroll
            for (int n8 = 0; n8 < 16; ++n8)
                #pragma unroll
                for (int c = 0; c < 4; ++c) acc[mt][n8][c] = 0.0f;

        #pragma unroll
        for (int kc = 0; kc < 8; ++kc) {
            // H1 fragments via tensor core: C(m16n8) layout == A-frag layout.
            uint32_t A[2][4];
            #pragma unroll
            for (int mt = 0; mt < 2; ++mt) {
                float cl[4] = {0, 0, 0, 0}, ch[4] = {0, 0, 0, 0};
                uint32_t af[4] = {ab[mt][0], ab[mt][1], 0u, 0u};
                mma_fp16(cl, af, W1B[kc][0], W1B[kc][1]);   // H1 cols 16kc+0..7
                mma_fp16(ch, af, W1B[kc][2], W1B[kc][3]);   // H1 cols 16kc+8..15
                A[mt][0] = h2pack(fmaxf(cl[0], 0.0f), fmaxf(cl[1], 0.0f));
                A[mt][1] = h2pack(fmaxf(cl[2], 0.0f), fmaxf(cl[3], 0.0f));
                A[mt][2] = h2pack(fmaxf(ch[0], 0.0f), fmaxf(ch[1], 0.0f));
                A[mt][3] = h2pack(fmaxf(ch[2], 0.0f), fmaxf(ch[3], 0.0f));
            }
            #pragma unroll
            for (int ng = 0; ng < 8; ++ng) {
                uint32_t B[4];
                ldsm_x4(B, w2b + SWZ(ng * 16 + brow_base, kc * 2 + bsel));
                mma_fp16(acc[0][2 * ng],     A[0], B[0], B[1]);
                mma_fp16(acc[0][2 * ng + 1], A[0], B[2], B[3]);
                mma_fp16(acc[1][2 * ng],     A[1], B[0], B[1]);
                mma_fp16(acc[1][2 * ng + 1], A[1], B[2], B[3]);
            }
        }

        // ---- epilogue: relu(H2+b2) @ W3; each warp completes its 32 rows ----
        float4* redc = sRed + (k & 1) * 128;
        #pragma unroll
        for (int mt = 0; mt < 2; ++mt) {
            float ov[2][4] = {{0,0,0,0},{0,0,0,0}};
            #pragma unroll
            for (int n8 = 0; n8 < 16; ++n8) {
                const int e0 = n8 * 8 + 2 * t4;
                const float2 b2v = *(const float2*)(sb2 + e0);
                const float4 w30 = *(const float4*)(sW3 + e0 * 4);
                const float4 w31 = *(const float4*)(sW3 + (e0 + 1) * 4);
                float h00 = fmaxf(acc[mt][n8][0] + b2v.x, 0.0f);
                float h01 = fmaxf(acc[mt][n8][1] + b2v.y, 0.0f);
                float h10 = fmaxf(acc[mt][n8][2] + b2v.x, 0.0f);
                float h11 = fmaxf(acc[mt][n8][3] + b2v.y, 0.0f);
                ov[0][0] = fmaf(h00, w30.x, fmaf(h01, w31.x, ov[0][0]));
                ov[0][1] = fmaf(h00, w30.y, fmaf(h01, w31.y, ov[0][1]));
                ov[0][2] = fmaf(h00, w30.z, fmaf(h01, w31.z, ov[0][2]));
                ov[0][3] = fmaf(h00, w30.w, fmaf(h01, w31.w, ov[0][3]));
                ov[1][0] = fmaf(h10, w30.x, fmaf(h11, w31.x, ov[1][0]));
                ov[1][1] = fmaf(h10, w30.y, fmaf(h11, w31.y, ov[1][1]));
                ov[1][2] = fmaf(h10, w30.z, fmaf(h11, w31.z, ov[1][2]));
                ov[1][3] = fmaf(h10, w30.w, fmaf(h11, w31.w, ov[1][3]));
            }
            #pragma unroll
            for (int h = 0; h < 2; ++h)
                #pragma unroll
                for (int o = 0; o < 4; ++o) {
                    float v = ov[h][o];
                    v += __shfl_xor_sync(0xFFFFFFFF, v, 1);
                    v += __shfl_xor_sync(0xFFFFFFFF, v, 2);
                    ov[h][o] = v;
                }
            if (t4 == 0) {
                redc[wid * 32 + mt * 16 + g]     = make_float4(ov[0][0], ov[0][1], ov[0][2], ov[0][3]);
                redc[wid * 32 + mt * 16 + 8 + g] = make_float4(ov[1][0], ov[1][1], ov[1][2], ov[1][3]);
            }
        }
        __syncthreads();   // single barrier per iteration

        {
            const float4 r = redc[tid];
            const int it = TILE_AT(k);
            const int jt = it & 3;
            const int i  = (it >> 2) & (ID - 1);
            const int b  = it >> 11;
            const long base = ((long)(b * 4) * ID + i) * JD + jt * MROWS + tid;
            const long os   = (long)ID * JD;
            out[base]          = r.x + sb3[0];
            out[base + os]     = r.y + sb3[1];
            out[base + 2 * os] = r.z + sb3[2];
            out[base + 3 * os] = r.w + sb3[3];
        }
    }
}

extern "C" void kernel_launch(void* const* d_in, const int* in_sizes, int n_in,
                              void* d_out, int out_size)
{
    const float* grid_q  = (const float*)d_in[0];
    const float* grid_kv = (const float*)d_in[1];
    const float* W1      = (const float*)d_in[2];
    const float* b1      = (const float*)d_in[3];
    const float* W2      = (const float*)d_in[4];
    const float* b2      = (const float*)d_in[5];
    const float* W3      = (const float*)d_in[6];
    const float* b3      = (const float*)d_in[7];
    float* out = (float*)d_out;

    prep_w2<<<DD * DD / 256, 256>>>(W2);

    cudaFuncSetAttribute(crpb_kernel,
                         cudaFuncAttributeMaxDynamicSharedMemorySize, SMEM_BYTES);
    crpb_kernel<<<GRIDSZ, NTHREADS, SMEM_BYTES>>>(
        grid_q, grid_kv, W1, b1, b2, W3, b3, out);
}